// round 9
// baseline (speedup 1.0000x reference)
#include <cuda_runtime.h>

// MPM p2g scatter: 1M particles -> 128^3 grid of (mass, mom.x, mom.y, mom.z)
// R8: single persistent fused kernel: zero phase + software grid barrier +
// corner-parallel v4-REDG scatter (R7 body, which sits at the measured REDG
// wavefront floor of ~4.5 lines/particle x ~2.07 cyc). Removes the separate
// memset node + inter-kernel gap (~5.8us of the 41.8us total).
//
// Grid barrier is graph-replay-safe: a monotonic epoch-ticket counter. Each
// launch adds exactly gridDim.x arrivals, so ticket/gridDim.x identifies the
// epoch and the wait target is (epoch+1)*gridDim.x. No reset, deterministic.
// Deadlock-free because 592 blocks = 148 SMs x 4 co-resident blocks
// (enforced via __launch_bounds__(256, 4); 8KB smem/block, <=64 regs).

static constexpr float INV_CELL = 64.0f;
static constexpr int NBLOCKS = 592;   // 148 SMs x 4 blocks (GB300 has 152: still resident)

__device__ unsigned int g_arrive = 0; // monotonic across graph replays

__device__ __forceinline__ void red_add_v4(float* p, float a, float b, float c, float d) {
    asm volatile("red.global.add.v4.f32 [%0], {%1, %2, %3, %4};"
                 :: "l"(p), "f"(a), "f"(b), "f"(c), "f"(d)
                 : "memory");
}

static constexpr int WARP_F4 = 64;    // per-warp stage: 64 float4 = 1KB

__global__ __launch_bounds__(256, 4) void p2g_fused_kernel(
    const float* __restrict__ pos,
    const float* __restrict__ vel,
    const float* __restrict__ mass,
    float* __restrict__ out,
    int n, int total_f4)              // total_f4 = out float4 count
{
    __shared__ float4 stage[8 * WARP_F4];
    __shared__ unsigned int s_target;

    int tid = threadIdx.x;
    int lane = tid & 31;
    int wib = tid >> 5;

    // ---- Phase 1: zero the output grid (grid-strided float4 stores) ----
    float4* out4 = (float4*)out;
    for (int i = blockIdx.x * 256 + tid; i < total_f4; i += NBLOCKS * 256)
        out4[i] = make_float4(0.f, 0.f, 0.f, 0.f);

    // ---- Grid barrier (epoch-ticket, release/acquire via threadfence) ----
    __threadfence();                  // publish zero-stores to L2
    __syncthreads();
    if (tid == 0) {
        unsigned int t = atomicAdd(&g_arrive, 1u);
        unsigned int target = (t / gridDim.x + 1u) * gridDim.x;
        s_target = target;
        while (atomicAdd(&g_arrive, 0u) < target) { }
    }
    __syncthreads();
    __threadfence();                  // acquire: other blocks' zeroes visible

    // ---- Phase 2: corner-parallel scatter over persistent warp-tiles ----
    float4* pm = stage + wib * WARP_F4;   // (fx,fy,fz,m) per particle
    float4* vl = pm + 32;                 // (vx,vy,vz,bitcast(base)) per particle
    float* pmf = (float*)pm;
    float* vlf = (float*)vl;

    const float4* pos4 = (const float4*)pos;
    const float4* vel4 = (const float4*)vel;
    const float4* mass4 = (const float4*)mass;

    int n_tiles = (n + 31) / 32;          // 32 particles per tile
    int p_local = lane >> 3;
    int c = lane & 7;                     // bit0=z, bit1=x, bit2=y
    int cz = c & 1, cx = (c >> 1) & 1, cy = (c >> 2) & 1;
    float axw = cx ? 1.f : -1.f, bxw = cx ? 0.f : 1.f;
    float ayw = cy ? 1.f : -1.f, byw = cy ? 0.f : 1.f;
    float azw = cz ? 1.f : -1.f, bzw = cz ? 0.f : 1.f;
    int coff = cz + (cx << 7) + (cy << 14);

    for (int tile = blockIdx.x * 8 + wib; tile < n_tiles; tile += NBLOCKS * 8) {
        int base = tile * 32;

        if (base + 32 <= n) {
            // Stage A: 3 coalesced LDG.128 per warp, repack padded
            if (lane < 24) {
                float4 p4 = pos4[tile * 24 + lane];
                float4 v4 = vel4[tile * 24 + lane];
                int j = 4 * lane;
#pragma unroll
                for (int t = 0; t < 4; t++) {
                    int q = (j + t) / 3, r = (j + t) % 3;
                    pmf[q * 4 + r] = (&p4.x)[t] * INV_CELL;
                    vlf[q * 4 + r] = (&v4.x)[t];
                }
            } else {
                float4 m4 = mass4[tile * 8 + (lane - 24)];
                int q0 = 4 * (lane - 24);
#pragma unroll
                for (int t = 0; t < 4; t++)
                    pmf[(q0 + t) * 4 + 3] = (&m4.x)[t];
            }
            __syncwarp();

            // Stage B: per-particle floor/frac/base-hash, once
            {
                float4 r4 = pm[lane];
                float bx = floorf(r4.x), by = floorf(r4.y), bz = floorf(r4.z);
                int bh = (int)bz + ((int)bx << 7) + ((int)by << 14);
                pm[lane] = make_float4(r4.x - bx, r4.y - by, r4.z - bz, r4.w);
                vlf[lane * 4 + 3] = __int_as_float(bh);
            }
            __syncwarp();

            // Scatter: 8 lanes/particle, 4 particles per warp REDG
#pragma unroll
            for (int s = 0; s < 8; s++) {
                int idx = s * 4 + p_local;
                float4 f4 = pm[idx];
                float4 v4 = vl[idx];
                float wx = fmaf(axw, f4.x, bxw);
                float wy = fmaf(ayw, f4.y, byw);
                float wz = fmaf(azw, f4.z, bzw);
                float sm = wx * wy * wz * f4.w;
                int hash = __float_as_int(v4.w) + coff;
                red_add_v4(out + 4 * hash, sm, sm * v4.x, sm * v4.y, sm * v4.z);
            }
            __syncwarp();
        } else {
            // Tail tile (n % 32 != 0 only): per-lane scalar path
            int pidx = base + lane;
            if (pidx < n) {
                float rx = pos[3 * pidx + 0] * INV_CELL;
                float ry = pos[3 * pidx + 1] * INV_CELL;
                float rz = pos[3 * pidx + 2] * INV_CELL;
                float vx = vel[3 * pidx + 0];
                float vy = vel[3 * pidx + 1];
                float vz = vel[3 * pidx + 2];
                float m  = mass[pidx];
                float bx = floorf(rx), by = floorf(ry), bz = floorf(rz);
                float fx = rx - bx, fy = ry - by, fz = rz - bz;
                int bh = (int)bz + ((int)bx << 7) + ((int)by << 14);
#pragma unroll
                for (int cc = 0; cc < 8; cc++) {
                    int z = cc & 1, x = (cc >> 1) & 1, y = (cc >> 2) & 1;
                    float w = (x ? fx : 1.f - fx) * (y ? fy : 1.f - fy) * (z ? fz : 1.f - fz);
                    float sm = w * m;
                    int hash = bh + z + (x << 7) + (y << 14);
                    red_add_v4(out + 4 * hash, sm, sm * vx, sm * vy, sm * vz);
                }
            }
        }
    }
    // s_target kept to prevent the compiler eliding the shared flag store.
    (void)s_target;
}

extern "C" void kernel_launch(void* const* d_in, const int* in_sizes, int n_in,
                              void* d_out, int out_size) {
    const float* pos  = (const float*)d_in[0];
    const float* vel  = (const float*)d_in[1];
    const float* mass = (const float*)d_in[2];
    float* out = (float*)d_out;

    int n = in_sizes[2];              // mass count = NUM_POINTS
    int total_f4 = out_size / 4;      // output float4 count
    p2g_fused_kernel<<<NBLOCKS, 256>>>(pos, vel, mass, out, n, total_f4);
}

// round 10
// speedup vs baseline: 1.0969x; 1.0969x over previous
#include <cuda_runtime.h>

// MPM p2g scatter: 1M particles -> 128^3 grid of (mass, mom.x, mom.y, mom.z)
// R9: R5 scatter body (corner-parallel v4 REDG, at the measured REDG
// wavefront floor of ~4.5 lines/particle x ~2.07 cyc) + PDL overlap:
// the scatter kernel launches programmatically-dependent on the zero kernel,
// runs its load/stage phase concurrently with zeroing, and calls
// cudaGridDependencySynchronize() only before the first REDG. The zero
// kernel triggers launch completion right after its stores.
// R8 lesson (reverted): fusing with a software grid barrier costs more than
// the memset it absorbs; PDL keeps the graph-edge semantics but overlaps
// the independent front-end work.

static constexpr float INV_CELL = 64.0f;

__device__ __forceinline__ void red_add_v4(float* p, float a, float b, float c, float d) {
    asm volatile("red.global.add.v4.f32 [%0], {%1, %2, %3, %4};"
                 :: "l"(p), "f"(a), "f"(b), "f"(c), "f"(d)
                 : "memory");
}

__global__ __launch_bounds__(256) void zero_out_kernel(float4* __restrict__ out, int n4) {
    int stride = gridDim.x * blockDim.x;
    for (int i = blockIdx.x * blockDim.x + threadIdx.x; i < n4; i += stride)
        out[i] = make_float4(0.f, 0.f, 0.f, 0.f);
    // Allow the dependent scatter grid to start launching now; its REDGs
    // still wait on full completion via cudaGridDependencySynchronize().
    cudaTriggerProgrammaticLaunchCompletion();
}

// Per-warp staging: pos[96] | vel[96] | mass[32] floats = 224 floats (896B).
static constexpr int WARP_STAGE = 224;

__global__ __launch_bounds__(256) void p2g_corner_kernel(
    const float* __restrict__ pos,
    const float* __restrict__ vel,
    const float* __restrict__ mass,
    float* __restrict__ out,
    int n)
{
    __shared__ float stage[8 * WARP_STAGE];   // 8 warps/block

    int warp_id = (blockIdx.x * blockDim.x + threadIdx.x) >> 5;  // global warp
    int lane = threadIdx.x & 31;
    int wib = threadIdx.x >> 5;
    float* sp = stage + wib * WARP_STAGE;     // [0,96) pos, [96,192) vel, [192,224) mass

    int base = warp_id * 32;                  // 32 particles per warp
    if (base >= n) {
        cudaGridDependencySynchronize();
        return;
    }

    // ---- front end (overlaps the zero kernel under PDL) ----
    if (base + 32 <= n) {
        const float4* pos4 = (const float4*)pos;
        const float4* vel4 = (const float4*)vel;
        const float4* mass4 = (const float4*)mass;
        if (lane < 24) {
            ((float4*)sp)[lane]        = pos4[warp_id * 24 + lane];   // 96 floats
            ((float4*)(sp + 96))[lane] = vel4[warp_id * 24 + lane];   // 96 floats
        } else {
            ((float4*)(sp + 192))[lane - 24] = mass4[warp_id * 8 + (lane - 24)]; // 32
        }
    } else {
        int nv = n - base;                    // tail warp, rare path
        for (int e = lane; e < nv * 3; e += 32) {
            sp[e]      = pos[base * 3 + e];
            sp[96 + e] = vel[base * 3 + e];
        }
        if (lane < nv) sp[192 + lane] = mass[base + lane];
    }
    __syncwarp();

    int p_local = lane >> 3;                  // particle within sub-iteration
    int c = lane & 7;                         // corner: bit0=z, bit1=x, bit2=y
    int cz = c & 1;
    int cx = (c >> 1) & 1;
    int cy = (c >> 2) & 1;

    // ---- wait for the zero kernel to fully complete, then scatter ----
    cudaGridDependencySynchronize();

#pragma unroll
    for (int s = 0; s < 8; s++) {
        int idx = s * 4 + p_local;            // particle index within warp
        if (base + idx < n) {
            float px = sp[3 * idx + 0];
            float py = sp[3 * idx + 1];
            float pz = sp[3 * idx + 2];
            float vx = sp[96 + 3 * idx + 0];
            float vy = sp[96 + 3 * idx + 1];
            float vz = sp[96 + 3 * idx + 2];
            float m  = sp[192 + idx];

            float rx = px * INV_CELL;
            float ry = py * INV_CELL;
            float rz = pz * INV_CELL;
            float bx = floorf(rx), by = floorf(ry), bz = floorf(rz);
            float fx = rx - bx, fy = ry - by, fz = rz - bz;

            float wxv = cx ? fx : 1.f - fx;
            float wyv = cy ? fy : 1.f - fy;
            float wzv = cz ? fz : 1.f - fz;

            // hash = z + x*128 + y*128*128 (all corners guaranteed in range)
            int hash = ((int)bz + cz) + (((int)bx + cx) << 7) + (((int)by + cy) << 14);

            float sm = wxv * wyv * wzv * m;
            red_add_v4(out + 4 * hash, sm, sm * vx, sm * vy, sm * vz);
        }
    }
}

extern "C" void kernel_launch(void* const* d_in, const int* in_sizes, int n_in,
                              void* d_out, int out_size) {
    const float* pos  = (const float*)d_in[0];
    const float* vel  = (const float*)d_in[1];
    const float* mass = (const float*)d_in[2];
    float* out = (float*)d_out;

    // Zero kernel: sized for full-chip store throughput.
    int n4 = out_size / 4;
    zero_out_kernel<<<2048, 256>>>((float4*)out, n4);

    // Scatter kernel, programmatically dependent on the zero kernel.
    int n = in_sizes[2];                      // mass count = NUM_POINTS
    int warps = (n + 31) / 32;
    int blocks = (warps + 7) / 8;             // 8 warps (256 threads) per block

    cudaLaunchConfig_t cfg = {};
    cfg.gridDim = dim3(blocks, 1, 1);
    cfg.blockDim = dim3(256, 1, 1);
    cfg.dynamicSmemBytes = 0;
    cfg.stream = 0;                           // legacy default stream (captured)
    cudaLaunchAttribute attr[1];
    attr[0].id = cudaLaunchAttributeProgrammaticStreamSerialization;
    attr[0].val.programmaticStreamSerializationAllowed = 1;
    cfg.attrs = attr;
    cfg.numAttrs = 1;
    cudaLaunchKernelEx(&cfg, p2g_corner_kernel, pos, vel, mass, out, n);
}